// round 11
// baseline (speedup 1.0000x reference)
#include <cuda_runtime.h>
#include <cuda_fp16.h>
#include <math.h>
#include <stdint.h>

#define NBATCH 4
#define IMG    256
#define C      128
#define ACTPTS 32768
#define NPTS   (NBATCH*ACTPTS)
#define TD     512
#define ZD     256
#define LN_EPS 1e-5f

// g_h1f: modulated input, fp16x2 words in FRAGMENT-PERMUTED order per point:
//   orig word w (0..63) stored at pos = (w>>5)*32 + (((w&31)>>3)*4 + (w&3))*2 + ((w&7)>>2)
//   so pairs (w, w+4) are adjacent -> uint2 LDG fetches a full A/B fragment k-pair.
__device__ uint32_t g_h1f[(size_t)NPTS * 64];
__device__ float    g_x [(size_t)NPTS * C];
__device__ int      g_grid[NBATCH * IMG * IMG];
__device__ float g_tt1[NBATCH*2*C], g_tt2[NBATCH*2*C], g_zz1[NBATCH*C], g_zz2[NBATCH*C];
__device__ uint32_t g_wct[49 * 128 * 64];        // conv w^T fp16x2, same permuted order
__device__ uint32_t g_w1t[256 * 64];             // mlp weights: UNCHANGED layout
__device__ uint32_t g_w2t[128 * 128];

__device__ __forceinline__ float gelu_exact(float x) {
    return 0.5f * x * (1.0f + erff(x * 0.70710678118654752440f));
}
__device__ __forceinline__ uint32_t pack_h2(float a, float b) {
    __half2 h = __floats2half2_rn(a, b);
    return *(uint32_t*)&h;
}
__device__ __forceinline__ int perm_pos(int w) {          // fragment permutation
    int ch = w >> 5, r = w & 31, ks = r >> 3, rem = r & 7;
    return ch*32 + (ks*4 + (rem & 3))*2 + (rem >> 2);
}
__device__ __forceinline__ void mma_f16(float* d, const uint32_t* a, const uint32_t* b) {
    asm volatile("mma.sync.aligned.m16n8k16.row.col.f32.f16.f16.f32 "
        "{%0,%1,%2,%3},{%4,%5,%6,%7},{%8,%9},{%0,%1,%2,%3};\n"
        : "+f"(d[0]), "+f"(d[1]), "+f"(d[2]), "+f"(d[3])
        : "r"(a[0]), "r"(a[1]), "r"(a[2]), "r"(a[3]), "r"(b[0]), "r"(b[1]));
}

// ---------------- launch 1: grid fill ----------------
__global__ void fill_grid_kernel() { g_grid[blockIdx.x * 256 + threadIdx.x] = -1; }

// ---------------- launch 2: fused init (scatter + modvec + fp16 weight pack) --------
#define NCONVW (49*128*64)
#define NW1W   (256*64)
#define NW2W   (128*128)
#define SPLIT_BLKS ((NCONVW + NW1W + NW2W) / 256)   // 1696
__global__ void fused_init_kernel(
    const int* __restrict__ xidx,
    const float* __restrict__ t,   const float* __restrict__ z,
    const float* __restrict__ t1w, const float* __restrict__ t1b,
    const float* __restrict__ t2w, const float* __restrict__ t2b,
    const float* __restrict__ z1w1, const float* __restrict__ z1b1,
    const float* __restrict__ z1w2, const float* __restrict__ z1b2,
    const float* __restrict__ z2w1, const float* __restrict__ z2b1,
    const float* __restrict__ z2w2, const float* __restrict__ z2b2,
    const float* __restrict__ convw, const float* __restrict__ w1, const float* __restrict__ w2)
{
    const int bid = blockIdx.x, tid = threadIdx.x;
    __shared__ float sbuf[768];
    if (bid < 512) {                       // scatter
        int n = bid * 256 + tid;
        g_grid[(xidx[3*n] << 16) | (xidx[3*n+1] << 8) | xidx[3*n+2]] = n;
    } else if (bid < 520) {                // modvec
        const int b = (bid - 512) >> 1;
        if (((bid - 512) & 1) == 0) {
            float* gt = sbuf;
            gt[tid] = gelu_exact(t[b*TD + tid]);
            gt[tid + 256] = gelu_exact(t[b*TD + tid + 256]);
            __syncthreads();
            float a1 = t1b[tid], a2 = t2b[tid];
            #pragma unroll 8
            for (int k = 0; k < TD; k++) { float g = gt[k]; a1 += g*t1w[k*256+tid]; a2 += g*t2w[k*256+tid]; }
            g_tt1[b*256 + tid] = a1; g_tt2[b*256 + tid] = a2;
        } else {
            float* gz = sbuf; float* hz = sbuf + 256;
            gz[tid] = z[b*ZD + tid];
            __syncthreads();
            {
                int j = tid & 127;
                const float* w = (tid < 128) ? z1w1 : z2w1;
                const float* bb = (tid < 128) ? z1b1 : z2b1;
                float a = bb[j];
                #pragma unroll 8
                for (int k = 0; k < ZD; k++) a += gz[k] * w[k*C + j];
                hz[tid] = gelu_exact(a);
            }
            __syncthreads();
            {
                int j = tid & 127;
                const float* w = (tid < 128) ? z1w2 : z2w2;
                const float* bb = (tid < 128) ? z1b2 : z2b2;
                const float* h = (tid < 128) ? hz : (hz + C);
                float a = bb[j];
                #pragma unroll 8
                for (int k = 0; k < C; k++) a += h[k] * w[k*C + j];
                if (tid < 128) g_zz1[b*C + j] = a; else g_zz2[b*C + j] = a;
            }
        }
    } else {                               // fp16 weight pack
        int i = (bid - 520) * 256 + tid;
        if (i < NCONVW) {
            int p = i & 63, rest = i >> 6;
            int cout = rest & 127, tap = rest >> 7;
            g_wct[(tap*128 + cout)*64 + perm_pos(p)] =                 // permuted
                pack_h2(convw[(tap*128 + 2*p + 0)*128 + cout], convw[(tap*128 + 2*p + 1)*128 + cout]);
        } else if (i < NCONVW + NW1W) {
            int j = i - NCONVW, p = j & 63, n = j >> 6;
            g_w1t[n*64 + p] = pack_h2(w1[(2*p+0)*256 + n], w1[(2*p+1)*256 + n]);
        } else {
            int j = i - (NCONVW + NW1W), p = j & 127, n = j >> 7;
            g_w2t[n*128 + p] = pack_h2(w2[(2*p+0)*128 + n], w2[(2*p+1)*128 + n]);
        }
    }
}

// ---------------- launch 3: LN1 + modulation -> fp16 (fragment-permuted) ------------
__global__ void modulate1_kernel(const float* __restrict__ xf,
                                 const float* __restrict__ lnw, const float* __restrict__ lnb) {
    const int warp = threadIdx.x >> 5, lane = threadIdx.x & 31;
    const int n = blockIdx.x * 8 + warp, b = n >> 15;
    float4 v = *(const float4*)(xf + (size_t)n*C + lane*4);
    float s = v.x + v.y + v.z + v.w;
    float sq = v.x*v.x + v.y*v.y + v.z*v.z + v.w*v.w;
    #pragma unroll
    for (int o = 16; o; o >>= 1) {
        s  += __shfl_xor_sync(0xffffffffu, s,  o);
        sq += __shfl_xor_sync(0xffffffffu, sq, o);
    }
    float mu = s * (1.0f/C);
    float rs = rsqrtf(sq*(1.0f/C) - mu*mu + LN_EPS);
    float vv[4] = {v.x, v.y, v.z, v.w}, o4[4];
    #pragma unroll
    for (int u = 0; u < 4; u++) {
        int c = lane*4 + u;
        float f = (vv[u] - mu)*rs*lnw[c] + lnb[c];
        f = f*(1.0f + g_tt1[b*256 + c]) + g_tt1[b*256 + 128 + c];
        o4[u] = f*(1.0f + g_zz1[b*128 + c]);
    }
    uint32_t w0 = pack_h2(o4[0], o4[1]);
    uint32_t w1 = pack_h2(o4[2], o4[3]);
    g_h1f[(size_t)n*64 + perm_pos(lane*2)]     = w0;
    g_h1f[(size_t)n*64 + perm_pos(lane*2 + 1)] = w1;
}

// ---------------- launch 4: conv — no smem, direct-LDG fragments --------------------
__global__ __launch_bounds__(256, 2) void conv_kernel(
    const float* __restrict__ xf, const float* __restrict__ nrm, const int* __restrict__ xidx) {
    const int tid = threadIdx.x, warp = tid >> 5, lane = tid & 31;
    const int wm = warp >> 1, wn = warp & 1;
    const int lq = lane >> 2, lr = lane & 3;
    const int base = blockIdx.x * 128;

    // this thread's 4 A rows: wm*32 + i*8 + lq  (i=0..3); whole CTA is one batch
    const int bb16 = xidx[3*base] << 16;
    int ry[4], rx[4];
    #pragma unroll
    for (int i = 0; i < 4; i++) {
        int n = base + wm*32 + i*8 + lq;
        ry[i] = xidx[3*n + 1];
        rx[i] = xidx[3*n + 2];
    }

    float acc[2][8][4];
    #pragma unroll
    for (int mt = 0; mt < 2; mt++)
        #pragma unroll
        for (int nj = 0; nj < 8; nj++)
            #pragma unroll
            for (int q = 0; q < 4; q++) acc[mt][nj][q] = 0.0f;

    const uint32_t* const wbase = g_wct + (size_t)(wn*64 + lq)*64;

    for (int tap = 0; tap < 49; tap++) {
        const int dy = tap/7 - 3, dx = tap%7 - 3;
        const uint32_t* ap[4];
        #pragma unroll
        for (int i = 0; i < 4; i++) {
            int ny = ry[i] + dy, nx = rx[i] + dx;
            int nb = -1;
            if ((unsigned)ny < 256u && (unsigned)nx < 256u)
                nb = g_grid[bb16 | (ny << 8) | nx];
            ap[i] = (nb >= 0) ? (g_h1f + (size_t)nb*64) : (const uint32_t*)0;
        }
        const uint32_t* wt = wbase + (size_t)tap*128*64;

        #pragma unroll
        for (int ch = 0; ch < 2; ch++) {
            #pragma unroll
            for (int ks = 0; ks < 4; ks++) {
                const int off = ch*32 + (ks*4 + lr)*2;
                uint2 av[4];
                #pragma unroll
                for (int i = 0; i < 4; i++) {
                    uint2 v = make_uint2(0u, 0u);
                    if (ap[i]) v = *(const uint2*)(ap[i] + off);
                    av[i] = v;
                }
                uint2 bv[8];
                #pragma unroll
                for (int nj = 0; nj < 8; nj++)
                    bv[nj] = *(const uint2*)(wt + (size_t)nj*8*64 + off);
                #pragma unroll
                for (int nj = 0; nj < 8; nj++) {
                    uint32_t b[2] = { bv[nj].x, bv[nj].y };
                    #pragma unroll
                    for (int mt = 0; mt < 2; mt++) {
                        uint32_t a[4] = { av[2*mt].x, av[2*mt+1].x, av[2*mt].y, av[2*mt+1].y };
                        mma_f16(acc[mt][nj], a, b);
                    }
                }
            }
        }
    }

    #pragma unroll
    for (int mt = 0; mt < 2; mt++) {
        int m = wm*32 + mt*16 + lq;
        float inv0 = 1.0f / nrm[base + m];
        float inv8 = 1.0f / nrm[base + m + 8];
        #pragma unroll
        for (int nj = 0; nj < 8; nj++) {
            int nn = wn*64 + nj*8 + lr*2;
            int gm = base + m;
            float2 x0 = *(const float2*)(xf + (size_t)gm*C + nn);
            float2 o0 = { x0.x + acc[mt][nj][0]*inv0, x0.y + acc[mt][nj][1]*inv0 };
            *(float2*)(g_x + (size_t)gm*C + nn) = o0;
            gm += 8;
            float2 x1 = *(const float2*)(xf + (size_t)gm*C + nn);
            float2 o1 = { x1.x + acc[mt][nj][2]*inv8, x1.y + acc[mt][nj][3]*inv8 };
            *(float2*)(g_x + (size_t)gm*C + nn) = o1;
        }
    }
}

// ---------------- launch 5: LN2 + modulation + MLP (pure fp16) + residual -----------
#define AST2 68
#define HST  132
#define MLP_SMEM ((64*AST2 + 64*HST) * 4)    // 51200 B
__global__ __launch_bounds__(256) void mlp_kernel(
    const float* __restrict__ lnw, const float* __restrict__ lnb,
    const float* __restrict__ b1,  const float* __restrict__ b2, float* __restrict__ out) {
    extern __shared__ uint32_t smem[];
    uint32_t* As = smem;
    uint32_t* Hs = smem + 64 * AST2;
    const int tid = threadIdx.x, warp = tid >> 5, lane = tid & 31;
    const int lq = lane >> 2, lr = lane & 3;
    const int base = blockIdx.x * 64;

    #pragma unroll
    for (int rr = 0; rr < 8; rr++) {
        int rl = warp*8 + rr, n = base + rl, b = n >> 15;
        float4 v = *(const float4*)(g_x + (size_t)n*C + lane*4);
        float s = v.x+v.y+v.z+v.w, sq = v.x*v.x+v.y*v.y+v.z*v.z+v.w*v.w;
        #pragma unroll
        for (int o = 16; o; o >>= 1) {
            s  += __shfl_xor_sync(0xffffffffu, s,  o);
            sq += __shfl_xor_sync(0xffffffffu, sq, o);
        }
        float mu = s*(1.0f/C), rs = rsqrtf(sq*(1.0f/C) - mu*mu + LN_EPS);
        float vv[4] = {v.x,v.y,v.z,v.w}, o4[4];
        #pragma unroll
        for (int u = 0; u < 4; u++) {
            int c = lane*4 + u;
            float f = (vv[u]-mu)*rs*lnw[c] + lnb[c];
            f = f*(1.0f + g_tt2[b*256+c]) + g_tt2[b*256+128+c];
            o4[u] = f*(1.0f + g_zz2[b*128+c]);
        }
        uint2 pk = { pack_h2(o4[0], o4[1]), pack_h2(o4[2], o4[3]) };
        *(uint2*)(As + rl*AST2 + lane*2) = pk;
    }
    __syncthreads();

    float acc1[4][4][4];
    #pragma unroll
    for (int mt = 0; mt < 4; mt++)
        #pragma unroll
        for (int nj = 0; nj < 4; nj++)
            #pragma unroll
            for (int q = 0; q < 4; q++) acc1[mt][nj][q] = 0.0f;
    #pragma unroll
    for (int ks = 0; ks < 8; ks++) {
        uint32_t a[4][4];
        #pragma unroll
        for (int mt = 0; mt < 4; mt++) {
            const uint32_t* ap = As + (mt*16 + lq)*AST2 + ks*8 + lr;
            a[mt][0] = ap[0]; a[mt][1] = ap[8*AST2]; a[mt][2] = ap[4]; a[mt][3] = ap[8*AST2 + 4];
        }
        #pragma unroll
        for (int nj = 0; nj < 4; nj++) {
            const uint32_t* bp = g_w1t + (warp*32 + nj*8 + lq)*64 + ks*8 + lr;
            uint32_t b[2] = { bp[0], bp[4] };
            #pragma unroll
            for (int mt = 0; mt < 4; mt++)
                mma_f16(acc1[mt][nj], a[mt], b);
        }
    }
    #pragma unroll
    for (int nj = 0; nj < 4; nj++) {
        int nn = warp*32 + nj*8 + lr*2;
        float2 bb = *(const float2*)(b1 + nn);
        int wrd = warp*16 + nj*4 + lr;
        #pragma unroll
        for (int mt = 0; mt < 4; mt++) {
            int m0 = mt*16 + lq;
            Hs[m0*HST + wrd]     = pack_h2(gelu_exact(acc1[mt][nj][0]+bb.x), gelu_exact(acc1[mt][nj][1]+bb.y));
            Hs[(m0+8)*HST + wrd] = pack_h2(gelu_exact(acc1[mt][nj][2]+bb.x), gelu_exact(acc1[mt][nj][3]+bb.y));
        }
    }
    __syncthreads();

    float acc2[4][2][4];
    #pragma unroll
    for (int mt = 0; mt < 4; mt++)
        #pragma unroll
        for (int nj = 0; nj < 2; nj++)
            #pragma unroll
            for (int q = 0; q < 4; q++) acc2[mt][nj][q] = 0.0f;
    #pragma unroll
    for (int ks = 0; ks < 16; ks++) {
        uint32_t a[4][4];
        #pragma unroll
        for (int mt = 0; mt < 4; mt++) {
            const uint32_t* ap = Hs + (mt*16 + lq)*HST + ks*8 + lr;
            a[mt][0] = ap[0]; a[mt][1] = ap[8*HST]; a[mt][2] = ap[4]; a[mt][3] = ap[8*HST + 4];
        }
        #pragma unroll
        for (int nj = 0; nj < 2; nj++) {
            const uint32_t* bp = g_w2t + (warp*16 + nj*8 + lq)*128 + ks*8 + lr;
            uint32_t b[2] = { bp[0], bp[4] };
            #pragma unroll
            for (int mt = 0; mt < 4; mt++)
                mma_f16(acc2[mt][nj], a[mt], b);
        }
    }
    #pragma unroll
    for (int nj = 0; nj < 2; nj++) {
        int nn = warp*16 + nj*8 + lr*2;
        float2 bb = *(const float2*)(b2 + nn);
        #pragma unroll
        for (int mt = 0; mt < 4; mt++) {
            int m0 = mt*16 + lq;
            int gm = base + m0;
            float2 x = *(const float2*)(g_x + (size_t)gm*C + nn);
            float2 o = { x.x + acc2[mt][nj][0] + bb.x, x.y + acc2[mt][nj][1] + bb.y };
            *(float2*)(out + (size_t)gm*C + nn) = o;
            gm += 8;
            x = *(const float2*)(g_x + (size_t)gm*C + nn);
            o.x = x.x + acc2[mt][nj][2] + bb.x;
            o.y = x.y + acc2[mt][nj][3] + bb.y;
            *(float2*)(out + (size_t)gm*C + nn) = o;
        }
    }
}

extern "C" void kernel_launch(void* const* d_in, const int* in_sizes, int n_in,
                              void* d_out, int out_size) {
    const float* xf    = (const float*)d_in[0];
    const int*   xi    = (const int*)  d_in[1];
    const float* t     = (const float*)d_in[2];
    const float* z     = (const float*)d_in[3];
    const float* nrm   = (const float*)d_in[4];
    const float* ln1w  = (const float*)d_in[5];
    const float* ln1b  = (const float*)d_in[6];
    const float* ln2w  = (const float*)d_in[7];
    const float* ln2b  = (const float*)d_in[8];
    const float* convw = (const float*)d_in[9];
    const float* t1w   = (const float*)d_in[10];
    const float* t1b   = (const float*)d_in[11];
    const float* t2w   = (const float*)d_in[12];
    const float* t2b   = (const float*)d_in[13];
    const float* z1w1  = (const float*)d_in[14];
    const float* z1b1  = (const float*)d_in[15];
    const float* z1w2  = (const float*)d_in[16];
    const float* z1b2  = (const float*)d_in[17];
    const float* z2w1  = (const float*)d_in[18];
    const float* z2b1  = (const float*)d_in[19];
    const float* z2w2  = (const float*)d_in[20];
    const float* z2b2  = (const float*)d_in[21];
    const float* w1    = (const float*)d_in[22];
    const float* b1    = (const float*)d_in[23];
    const float* w2    = (const float*)d_in[24];
    const float* b2    = (const float*)d_in[25];
    float* out = (float*)d_out;

    cudaFuncSetAttribute(mlp_kernel, cudaFuncAttributeMaxDynamicSharedMemorySize, MLP_SMEM);

    fill_grid_kernel<<<(NBATCH*IMG*IMG)/256, 256>>>();
    fused_init_kernel<<<512 + 8 + SPLIT_BLKS, 256>>>(xi, t, z, t1w, t1b, t2w, t2b,
        z1w1, z1b1, z1w2, z1b2, z2w1, z2b1, z2w2, z2b2, convw, w1, w2);
    modulate1_kernel<<<NPTS/8, 256>>>(xf, ln1w, ln1b);
    conv_kernel<<<NPTS/128, 256>>>(xf, nrm, xi);
    mlp_kernel<<<NPTS/64, 256, MLP_SMEM>>>(ln2w, ln2b, b1, b2, out);
    (void)in_sizes; (void)n_in; (void)out_size;
}

// round 12
// speedup vs baseline: 1.1338x; 1.1338x over previous
#include <cuda_runtime.h>
#include <cuda_fp16.h>
#include <math.h>
#include <stdint.h>

#define NBATCH 4
#define IMG    256
#define C      128
#define ACTPTS 32768
#define NPTS   (NBATCH*ACTPTS)
#define TD     512
#define ZD     256
#define LN_EPS 1e-5f

// g_h1f: modulated input fp16x2, FRAGMENT-PERMUTED per point:
//   word w -> pos = (w>>5)*32 + (((w&31)>>3)*4 + (w&3))*2 + ((w&7)>>2)
__device__ uint32_t g_h1f[(size_t)NPTS * 64];
__device__ float    g_x [(size_t)NPTS * C];
__device__ int      g_grid[NBATCH * IMG * IMG];
__device__ float g_tt1[NBATCH*2*C], g_tt2[NBATCH*2*C], g_zz1[NBATCH*C], g_zz2[NBATCH*C];
__device__ uint32_t g_wct[49 * 128 * 64];        // conv w^T fp16x2, same permuted order
__device__ uint32_t g_w1t[256 * 64];             // mlp weights: plain layout
__device__ uint32_t g_w2t[128 * 128];

__device__ __forceinline__ float gelu_exact(float x) {
    return 0.5f * x * (1.0f + erff(x * 0.70710678118654752440f));
}
__device__ __forceinline__ uint32_t pack_h2(float a, float b) {
    __half2 h = __floats2half2_rn(a, b);
    return *(uint32_t*)&h;
}
__device__ __forceinline__ int perm_pos(int w) {
    int ch = w >> 5, r = w & 31, ks = r >> 3, rem = r & 7;
    return ch*32 + (ks*4 + (rem & 3))*2 + (rem >> 2);
}
__device__ __forceinline__ void mma_f16(float* d, const uint32_t* a, const uint32_t* b) {
    asm volatile("mma.sync.aligned.m16n8k16.row.col.f32.f16.f16.f32 "
        "{%0,%1,%2,%3},{%4,%5,%6,%7},{%8,%9},{%0,%1,%2,%3};\n"
        : "+f"(d[0]), "+f"(d[1]), "+f"(d[2]), "+f"(d[3])
        : "r"(a[0]), "r"(a[1]), "r"(a[2]), "r"(a[3]), "r"(b[0]), "r"(b[1]));
}
__device__ __forceinline__ uint32_t smem_u32(const void* p) {
    uint32_t a;
    asm("{ .reg .u64 t; cvta.to.shared.u64 t, %1; cvt.u32.u64 %0, t; }" : "=r"(a) : "l"(p));
    return a;
}
__device__ __forceinline__ void cp16(uint32_t dst, const void* src, uint32_t srcsize) {
    asm volatile("cp.async.ca.shared.global [%0], [%1], 16, %2;"
                 :: "r"(dst), "l"(src), "r"(srcsize) : "memory");
}
#define CP_COMMIT() asm volatile("cp.async.commit_group;" ::: "memory")
#define CP_WAIT1()  asm volatile("cp.async.wait_group 1;" ::: "memory")
#define CP_WAIT0()  asm volatile("cp.async.wait_group 0;" ::: "memory")

// ---------------- launch 1: grid fill ----------------
__global__ void fill_grid_kernel() { g_grid[blockIdx.x * 256 + threadIdx.x] = -1; }

// ---------------- launch 2: fused init (scatter + modvec + fp16 weight pack) --------
#define NCONVW (49*128*64)
#define NW1W   (256*64)
#define NW2W   (128*128)
#define SPLIT_BLKS ((NCONVW + NW1W + NW2W) / 256)   // 1696
__global__ void fused_init_kernel(
    const int* __restrict__ xidx,
    const float* __restrict__ t,   const float* __restrict__ z,
    const float* __restrict__ t1w, const float* __restrict__ t1b,
    const float* __restrict__ t2w, const float* __restrict__ t2b,
    const float* __restrict__ z1w1, const float* __restrict__ z1b1,
    const float* __restrict__ z1w2, const float* __restrict__ z1b2,
    const float* __restrict__ z2w1, const float* __restrict__ z2b1,
    const float* __restrict__ z2w2, const float* __restrict__ z2b2,
    const float* __restrict__ convw, const float* __restrict__ w1, const float* __restrict__ w2)
{
    const int bid = blockIdx.x, tid = threadIdx.x;
    __shared__ float sbuf[768];
    if (bid < 512) {
        int n = bid * 256 + tid;
        g_grid[(xidx[3*n] << 16) | (xidx[3*n+1] << 8) | xidx[3*n+2]] = n;
    } else if (bid < 520) {
        const int b = (bid - 512) >> 1;
        if (((bid - 512) & 1) == 0) {
            float* gt = sbuf;
            gt[tid] = gelu_exact(t[b*TD + tid]);
            gt[tid + 256] = gelu_exact(t[b*TD + tid + 256]);
            __syncthreads();
            float a1 = t1b[tid], a2 = t2b[tid];
            #pragma unroll 8
            for (int k = 0; k < TD; k++) { float g = gt[k]; a1 += g*t1w[k*256+tid]; a2 += g*t2w[k*256+tid]; }
            g_tt1[b*256 + tid] = a1; g_tt2[b*256 + tid] = a2;
        } else {
            float* gz = sbuf; float* hz = sbuf + 256;
            gz[tid] = z[b*ZD + tid];
            __syncthreads();
            {
                int j = tid & 127;
                const float* w = (tid < 128) ? z1w1 : z2w1;
                const float* bb = (tid < 128) ? z1b1 : z2b1;
                float a = bb[j];
                #pragma unroll 8
                for (int k = 0; k < ZD; k++) a += gz[k] * w[k*C + j];
                hz[tid] = gelu_exact(a);
            }
            __syncthreads();
            {
                int j = tid & 127;
                const float* w = (tid < 128) ? z1w2 : z2w2;
                const float* bb = (tid < 128) ? z1b2 : z2b2;
                const float* h = (tid < 128) ? hz : (hz + C);
                float a = bb[j];
                #pragma unroll 8
                for (int k = 0; k < C; k++) a += h[k] * w[k*C + j];
                if (tid < 128) g_zz1[b*C + j] = a; else g_zz2[b*C + j] = a;
            }
        }
    } else {
        int i = (bid - 520) * 256 + tid;
        if (i < NCONVW) {
            int p = i & 63, rest = i >> 6;
            int cout = rest & 127, tap = rest >> 7;
            g_wct[(tap*128 + cout)*64 + perm_pos(p)] =
                pack_h2(convw[(tap*128 + 2*p + 0)*128 + cout], convw[(tap*128 + 2*p + 1)*128 + cout]);
        } else if (i < NCONVW + NW1W) {
            int j = i - NCONVW, p = j & 63, n = j >> 6;
            g_w1t[n*64 + p] = pack_h2(w1[(2*p+0)*256 + n], w1[(2*p+1)*256 + n]);
        } else {
            int j = i - (NCONVW + NW1W), p = j & 127, n = j >> 7;
            g_w2t[n*128 + p] = pack_h2(w2[(2*p+0)*128 + n], w2[(2*p+1)*128 + n]);
        }
    }
}

// ---------------- launch 3: LN1 + modulation -> fp16 (fragment-permuted) ------------
__global__ void modulate1_kernel(const float* __restrict__ xf,
                                 const float* __restrict__ lnw, const float* __restrict__ lnb) {
    const int warp = threadIdx.x >> 5, lane = threadIdx.x & 31;
    const int n = blockIdx.x * 8 + warp, b = n >> 15;
    float4 v = *(const float4*)(xf + (size_t)n*C + lane*4);
    float s = v.x + v.y + v.z + v.w;
    float sq = v.x*v.x + v.y*v.y + v.z*v.z + v.w*v.w;
    #pragma unroll
    for (int o = 16; o; o >>= 1) {
        s  += __shfl_xor_sync(0xffffffffu, s,  o);
        sq += __shfl_xor_sync(0xffffffffu, sq, o);
    }
    float mu = s * (1.0f/C);
    float rs = rsqrtf(sq*(1.0f/C) - mu*mu + LN_EPS);
    float vv[4] = {v.x, v.y, v.z, v.w}, o4[4];
    #pragma unroll
    for (int u = 0; u < 4; u++) {
        int c = lane*4 + u;
        float f = (vv[u] - mu)*rs*lnw[c] + lnb[c];
        f = f*(1.0f + g_tt1[b*256 + c]) + g_tt1[b*256 + 128 + c];
        o4[u] = f*(1.0f + g_zz1[b*128 + c]);
    }
    uint32_t w0 = pack_h2(o4[0], o4[1]);
    uint32_t w1 = pack_h2(o4[2], o4[3]);
    g_h1f[(size_t)n*64 + perm_pos(lane*2)]     = w0;
    g_h1f[(size_t)n*64 + perm_pos(lane*2 + 1)] = w1;
}

// ---------------- launch 4: conv — R9 pipeline, swizzled pad-free staging -----------
#define ACH 16384                        // one chunk matrix: 128 rows x 128B
#define BUFB 32768                       // A + B
#define CONV_SMEM (2*BUFB)               // 65536 B -> 2 CTAs/SM
__device__ __forceinline__ int nbr_lookup(int myb, int myy, int myx, int tap) {
    int ny = myy + tap/7 - 3, nx = myx + tap%7 - 3;
    if ((unsigned)ny < 256u && (unsigned)nx < 256u) return g_grid[myb | (ny<<8) | nx];
    return -1;
}
// 16B-unit XOR swizzle: unit u at row stored at (u ^ (row&7))
__device__ __forceinline__ void stage_chunk(uint32_t Abuf, int tap, int ch,
                                            int nbr, int row, int hh) {
    const uint32_t sw = (uint32_t)(row & 7);
    const char* asrc = (const char*)g_h1f;
    uint32_t sz = 0;
    if (nbr >= 0) { asrc += (size_t)nbr*256 + ch*128 + hh*64; sz = 16; }
    uint32_t da = Abuf + (uint32_t)row*128;
    #pragma unroll
    for (int j = 0; j < 4; j++)
        cp16(da + (((uint32_t)(hh*4 + j) ^ sw) * 16), asrc + j*16, sz);
    const char* bsrc = (const char*)g_wct + (size_t)(tap*128 + row)*256 + ch*128 + hh*64;
    uint32_t db = Abuf + ACH + (uint32_t)row*128;
    #pragma unroll
    for (int j = 0; j < 4; j++)
        cp16(db + (((uint32_t)(hh*4 + j) ^ sw) * 16), bsrc + j*16, 16);
}

__global__ __launch_bounds__(256, 2) void conv_kernel(
    const float* __restrict__ xf, const float* __restrict__ nrm, const int* __restrict__ xidx) {
    extern __shared__ uint8_t smemraw[];
    const uint32_t sb32 = smem_u32(smemraw);
    const int tid = threadIdx.x, warp = tid >> 5, lane = tid & 31;
    const int wm = warp >> 1, wn = warp & 1;
    const int lq = lane >> 2, lr = lane & 3;
    const int base = blockIdx.x * 128;
    const int row = tid >> 1, hh = tid & 1;

    const int n0i = base + row;
    const int myb = xidx[3*n0i] << 16, myy = xidx[3*n0i+1], myx = xidx[3*n0i+2];

    float acc[2][8][4];
    #pragma unroll
    for (int mt = 0; mt < 2; mt++)
        #pragma unroll
        for (int nj = 0; nj < 8; nj++)
            #pragma unroll
            for (int q = 0; q < 4; q++) acc[mt][nj][q] = 0.0f;

    int nbr_s = nbr_lookup(myb, myy, myx, 0);
    int nbr_p = -1;
    stage_chunk(sb32, 0, 0, nbr_s, row, hh);
    CP_COMMIT();

    #pragma unroll 2
    for (int c = 0; c < 98; c++) {
        const int tap = c >> 1;
        if (c < 97) {
            const int c1 = c + 1;
            int nbr_use = (c1 & 1) ? nbr_s : nbr_p;
            if ((c1 & 1) == 0) nbr_s = nbr_p;
            stage_chunk(sb32 + (uint32_t)(c1 & 1)*BUFB, c1 >> 1, c1 & 1, nbr_use, row, hh);
            CP_COMMIT();
            CP_WAIT1();
        } else {
            CP_WAIT0();
        }
        __syncthreads();
        if ((c & 1) == 0 && tap + 1 < 49)
            nbr_p = nbr_lookup(myb, myy, myx, tap + 1);

        const uint8_t* As = smemraw + (uint32_t)(c & 1) * BUFB;
        const uint8_t* Bs = As + ACH;
        #pragma unroll
        for (int ks = 0; ks < 4; ks++) {
            const uint32_t soff = ((uint32_t)((2*ks + (lr >> 1)) ^ lq)) * 16 + (lr & 1) * 8;
            uint2 av[4];
            #pragma unroll
            for (int mt = 0; mt < 2; mt++) {
                int r0 = wm*32 + mt*16 + lq;
                av[2*mt]   = *(const uint2*)(As + (uint32_t)r0*128 + soff);
                av[2*mt+1] = *(const uint2*)(As + (uint32_t)(r0 + 8)*128 + soff);
            }
            uint2 bv[8];
            #pragma unroll
            for (int nj = 0; nj < 8; nj++) {
                int rb = wn*64 + nj*8 + lq;
                bv[nj] = *(const uint2*)(Bs + (uint32_t)rb*128 + soff);
            }
            #pragma unroll
            for (int nj = 0; nj < 8; nj++) {
                uint32_t b[2] = { bv[nj].x, bv[nj].y };
                #pragma unroll
                for (int mt = 0; mt < 2; mt++) {
                    uint32_t a[4] = { av[2*mt].x, av[2*mt+1].x, av[2*mt].y, av[2*mt+1].y };
                    mma_f16(acc[mt][nj], a, b);
                }
            }
        }
        __syncthreads();
    }

    #pragma unroll
    for (int mt = 0; mt < 2; mt++) {
        int m = wm*32 + mt*16 + lq;
        float inv0 = 1.0f / nrm[base + m];
        float inv8 = 1.0f / nrm[base + m + 8];
        #pragma unroll
        for (int nj = 0; nj < 8; nj++) {
            int nn = wn*64 + nj*8 + lr*2;
            int gm = base + m;
            float2 x0 = *(const float2*)(xf + (size_t)gm*C + nn);
            float2 o0 = { x0.x + acc[mt][nj][0]*inv0, x0.y + acc[mt][nj][1]*inv0 };
            *(float2*)(g_x + (size_t)gm*C + nn) = o0;
            gm += 8;
            float2 x1 = *(const float2*)(xf + (size_t)gm*C + nn);
            float2 o1 = { x1.x + acc[mt][nj][2]*inv8, x1.y + acc[mt][nj][3]*inv8 };
            *(float2*)(g_x + (size_t)gm*C + nn) = o1;
        }
    }
}

// ---------------- launch 5: LN2 + modulation + MLP (pure fp16) + residual -----------
#define AST2 68
#define HST  132
#define MLP_SMEM ((64*AST2 + 64*HST) * 4)    // 51200 B
__global__ __launch_bounds__(256) void mlp_kernel(
    const float* __restrict__ lnw, const float* __restrict__ lnb,
    const float* __restrict__ b1,  const float* __restrict__ b2, float* __restrict__ out) {
    extern __shared__ uint32_t smem[];
    uint32_t* As = smem;
    uint32_t* Hs = smem + 64 * AST2;
    const int tid = threadIdx.x, warp = tid >> 5, lane = tid & 31;
    const int lq = lane >> 2, lr = lane & 3;
    const int base = blockIdx.x * 64;

    #pragma unroll
    for (int rr = 0; rr < 8; rr++) {
        int rl = warp*8 + rr, n = base + rl, b = n >> 15;
        float4 v = *(const float4*)(g_x + (size_t)n*C + lane*4);
        float s = v.x+v.y+v.z+v.w, sq = v.x*v.x+v.y*v.y+v.z*v.z+v.w*v.w;
        #pragma unroll
        for (int o = 16; o; o >>= 1) {
            s  += __shfl_xor_sync(0xffffffffu, s,  o);
            sq += __shfl_xor_sync(0xffffffffu, sq, o);
        }
        float mu = s*(1.0f/C), rs = rsqrtf(sq*(1.0f/C) - mu*mu + LN_EPS);
        float vv[4] = {v.x,v.y,v.z,v.w}, o4[4];
        #pragma unroll
        for (int u = 0; u < 4; u++) {
            int c = lane*4 + u;
            float f = (vv[u]-mu)*rs*lnw[c] + lnb[c];
            f = f*(1.0f + g_tt2[b*256+c]) + g_tt2[b*256+128+c];
            o4[u] = f*(1.0f + g_zz2[b*128+c]);
        }
        uint2 pk = { pack_h2(o4[0], o4[1]), pack_h2(o4[2], o4[3]) };
        *(uint2*)(As + rl*AST2 + lane*2) = pk;
    }
    __syncthreads();

    float acc1[4][4][4];
    #pragma unroll
    for (int mt = 0; mt < 4; mt++)
        #pragma unroll
        for (int nj = 0; nj < 4; nj++)
            #pragma unroll
            for (int q = 0; q < 4; q++) acc1[mt][nj][q] = 0.0f;
    #pragma unroll
    for (int ks = 0; ks < 8; ks++) {
        uint32_t a[4][4];
        #pragma unroll
        for (int mt = 0; mt < 4; mt++) {
            const uint32_t* ap = As + (mt*16 + lq)*AST2 + ks*8 + lr;
            a[mt][0] = ap[0]; a[mt][1] = ap[8*AST2]; a[mt][2] = ap[4]; a[mt][3] = ap[8*AST2 + 4];
        }
        #pragma unroll
        for (int nj = 0; nj < 4; nj++) {
            const uint32_t* bp = g_w1t + (warp*32 + nj*8 + lq)*64 + ks*8 + lr;
            uint32_t b[2] = { bp[0], bp[4] };
            #pragma unroll
            for (int mt = 0; mt < 4; mt++)
                mma_f16(acc1[mt][nj], a[mt], b);
        }
    }
    #pragma unroll
    for (int nj = 0; nj < 4; nj++) {
        int nn = warp*32 + nj*8 + lr*2;
        float2 bb = *(const float2*)(b1 + nn);
        int wrd = warp*16 + nj*4 + lr;
        #pragma unroll
        for (int mt = 0; mt < 4; mt++) {
            int m0 = mt*16 + lq;
            Hs[m0*HST + wrd]     = pack_h2(gelu_exact(acc1[mt][nj][0]+bb.x), gelu_exact(acc1[mt][nj][1]+bb.y));
            Hs[(m0+8)*HST + wrd] = pack_h2(gelu_exact(acc1[mt][nj][2]+bb.x), gelu_exact(acc1[mt][nj][3]+bb.y));
        }
    }
    __syncthreads();

    float acc2[4][2][4];
    #pragma unroll
    for (int mt = 0; mt < 4; mt++)
        #pragma unroll
        for (int nj = 0; nj < 2; nj++)
            #pragma unroll
            for (int q = 0; q < 4; q++) acc2[mt][nj][q] = 0.0f;
    #pragma unroll
    for (int ks = 0; ks < 16; ks++) {
        uint32_t a[4][4];
        #pragma unroll
        for (int mt = 0; mt < 4; mt++) {
            const uint32_t* ap = Hs + (mt*16 + lq)*HST + ks*8 + lr;
            a[mt][0] = ap[0]; a[mt][1] = ap[8*HST]; a[mt][2] = ap[4]; a[mt][3] = ap[8*HST + 4];
        }
        #pragma unroll
        for (int nj = 0; nj < 2; nj++) {
            const uint32_t* bp = g_w2t + (warp*16 + nj*8 + lq)*128 + ks*8 + lr;
            uint32_t b[2] = { bp[0], bp[4] };
            #pragma unroll
            for (int mt = 0; mt < 4; mt++)
                mma_f16(acc2[mt][nj], a[mt], b);
        }
    }
    #pragma unroll
    for (int nj = 0; nj < 2; nj++) {
        int nn = warp*16 + nj*8 + lr*2;
        float2 bb = *(const float2*)(b2 + nn);
        #pragma unroll
        for (int mt = 0; mt < 4; mt++) {
            int m0 = mt*16 + lq;
            int gm = base + m0;
            float2 x = *(const float2*)(g_x + (size_t)gm*C + nn);
            float2 o = { x.x + acc2[mt][nj][0] + bb.x, x.y + acc2[mt][nj][1] + bb.y };
            *(float2*)(out + (size_t)gm*C + nn) = o;
            gm += 8;
            x = *(const float2*)(g_x + (size_t)gm*C + nn);
            o.x = x.x + acc2[mt][nj][2] + bb.x;
            o.y = x.y + acc2[mt][nj][3] + bb.y;
            *(float2*)(out + (size_t)gm*C + nn) = o;
        }
    }
}

extern "C" void kernel_launch(void* const* d_in, const int* in_sizes, int n_in,
                              void* d_out, int out_size) {
    const float* xf    = (const float*)d_in[0];
    const int*   xi    = (const int*)  d_in[1];
    const float* t     = (const float*)d_in[2];
    const float* z     = (const float*)d_in[3];
    const float* nrm   = (const float*)d_in[4];
    const float* ln1w  = (const float*)d_in[5];
    const float* ln1b  = (const float*)d_in[6];
    const float* ln2w  = (const float*)d_in[7];
    const float* ln2b  = (const float*)d_in[8];
    const float* convw = (const float*)d_in[9];
    const float* t1w   = (const float*)d_in[10];
    const float* t1b   = (const float*)d_in[11];
    const float* t2w   = (const float*)d_in[12];
    const float* t2b   = (const float*)d_in[13];
    const float* z1w1  = (const float*)d_in[14];
    const float* z1b1  = (const float*)d_in[15];
    const float* z1w2  = (const float*)d_in[16];
    const float* z1b2  = (const float*)d_in[17];
    const float* z2w1  = (const float*)d_in[18];
    const float* z2b1  = (const float*)d_in[19];
    const float* z2w2  = (const float*)d_in[20];
    const float* z2b2  = (const float*)d_in[21];
    const float* w1    = (const float*)d_in[22];
    const float* b1    = (const float*)d_in[23];
    const float* w2    = (const float*)d_in[24];
    const float* b2    = (const float*)d_in[25];
    float* out = (float*)d_out;

    cudaFuncSetAttribute(conv_kernel, cudaFuncAttributeMaxDynamicSharedMemorySize, CONV_SMEM);
    cudaFuncSetAttribute(mlp_kernel,  cudaFuncAttributeMaxDynamicSharedMemorySize, MLP_SMEM);

    fill_grid_kernel<<<(NBATCH*IMG*IMG)/256, 256>>>();
    fused_init_kernel<<<512 + 8 + SPLIT_BLKS, 256>>>(xi, t, z, t1w, t1b, t2w, t2b,
        z1w1, z1b1, z1w2, z1b2, z2w1, z2b1, z2w2, z2b2, convw, w1, w2);
    modulate1_kernel<<<NPTS/8, 256>>>(xf, ln1w, ln1b);
    conv_kernel<<<NPTS/128, 256, CONV_SMEM>>>(xf, nrm, xi);
    mlp_kernel<<<NPTS/64, 256, MLP_SMEM>>>(ln2w, ln2b, b1, b2, out);
    (void)in_sizes; (void)n_in; (void)out_size;
}

// round 14
// speedup vs baseline: 1.3653x; 1.2042x over previous
#include <cuda_runtime.h>
#include <cuda_fp16.h>
#include <math.h>
#include <stdint.h>

#define NBATCH 4
#define IMG    256
#define C      128
#define ACTPTS 32768
#define NPTS   (NBATCH*ACTPTS)
#define TD     512
#define ZD     256
#define LN_EPS 1e-5f

__device__ uint32_t g_h1f[(size_t)NPTS * 64];    // modulated input, fp16x2 words (plain order)
__device__ float    g_x [(size_t)NPTS * C];
__device__ int      g_grid[NBATCH * IMG * IMG];
__device__ float g_tt1[NBATCH*2*C], g_tt2[NBATCH*2*C], g_zz1[NBATCH*C], g_zz2[NBATCH*C];
__device__ uint32_t g_wct[49 * 128 * 64];        // conv w^T fp16x2: [tap][cout][64 words]
__device__ uint32_t g_w1t[256 * 64];             // w1^T fp16x2 (K=128)
__device__ uint32_t g_w2t[128 * 128];            // w2^T fp16x2 (K=256)

__device__ __forceinline__ float gelu_exact(float x) {
    return 0.5f * x * (1.0f + erff(x * 0.70710678118654752440f));
}
__device__ __forceinline__ uint32_t pack_h2(float a, float b) {
    __half2 h = __floats2half2_rn(a, b);
    return *(uint32_t*)&h;
}
__device__ __forceinline__ void mma_f16(float* d, const uint32_t* a, const uint32_t* b) {
    asm volatile("mma.sync.aligned.m16n8k16.row.col.f32.f16.f16.f32 "
        "{%0,%1,%2,%3},{%4,%5,%6,%7},{%8,%9},{%0,%1,%2,%3};\n"
        : "+f"(d[0]), "+f"(d[1]), "+f"(d[2]), "+f"(d[3])
        : "r"(a[0]), "r"(a[1]), "r"(a[2]), "r"(a[3]), "r"(b[0]), "r"(b[1]));
}
#define LDSM4(r, addr) \
    asm volatile("ldmatrix.sync.aligned.m8n8.x4.shared.b16 {%0,%1,%2,%3}, [%4];" \
        : "=r"((r)[0]), "=r"((r)[1]), "=r"((r)[2]), "=r"((r)[3]) : "r"(addr))
__device__ __forceinline__ uint32_t smem_u32(const void* p) {
    uint32_t a;
    asm("{ .reg .u64 t; cvta.to.shared.u64 t, %1; cvt.u32.u64 %0, t; }" : "=r"(a) : "l"(p));
    return a;
}
__device__ __forceinline__ void cp16(uint32_t dst, const void* src, uint32_t srcsize) {
    asm volatile("cp.async.ca.shared.global [%0], [%1], 16, %2;"
                 :: "r"(dst), "l"(src), "r"(srcsize) : "memory");
}
#define CP_COMMIT() asm volatile("cp.async.commit_group;" ::: "memory")
#define CP_WAIT1()  asm volatile("cp.async.wait_group 1;" ::: "memory")
#define CP_WAIT0()  asm volatile("cp.async.wait_group 0;" ::: "memory")

// ---------------- launch 1: grid fill ----------------
__global__ void fill_grid_kernel() { g_grid[blockIdx.x * 256 + threadIdx.x] = -1; }

// ---------------- launch 2: fused init (scatter + modvec + fp16 weight pack) --------
#define NCONVW (49*128*64)
#define NW1W   (256*64)
#define NW2W   (128*128)
#define SPLIT_BLKS ((NCONVW + NW1W + NW2W) / 256)   // 1696
__global__ void fused_init_kernel(
    const int* __restrict__ xidx,
    const float* __restrict__ t,   const float* __restrict__ z,
    const float* __restrict__ t1w, const float* __restrict__ t1b,
    const float* __restrict__ t2w, const float* __restrict__ t2b,
    const float* __restrict__ z1w1, const float* __restrict__ z1b1,
    const float* __restrict__ z1w2, const float* __restrict__ z1b2,
    const float* __restrict__ z2w1, const float* __restrict__ z2b1,
    const float* __restrict__ z2w2, const float* __restrict__ z2b2,
    const float* __restrict__ convw, const float* __restrict__ w1, const float* __restrict__ w2)
{
    const int bid = blockIdx.x, tid = threadIdx.x;
    __shared__ float sbuf[768];
    if (bid < 512) {
        int n = bid * 256 + tid;
        g_grid[(xidx[3*n] << 16) | (xidx[3*n+1] << 8) | xidx[3*n+2]] = n;
    } else if (bid < 520) {
        const int b = (bid - 512) >> 1;
        if (((bid - 512) & 1) == 0) {
            float* gt = sbuf;
            gt[tid] = gelu_exact(t[b*TD + tid]);
            gt[tid + 256] = gelu_exact(t[b*TD + tid + 256]);
            __syncthreads();
            float a1 = t1b[tid], a2 = t2b[tid];
            #pragma unroll 8
            for (int k = 0; k < TD; k++) { float g = gt[k]; a1 += g*t1w[k*256+tid]; a2 += g*t2w[k*256+tid]; }
            g_tt1[b*256 + tid] = a1; g_tt2[b*256 + tid] = a2;
        } else {
            float* gz = sbuf; float* hz = sbuf + 256;
            gz[tid] = z[b*ZD + tid];
            __syncthreads();
            {
                int j = tid & 127;
                const float* w = (tid < 128) ? z1w1 : z2w1;
                const float* bb = (tid < 128) ? z1b1 : z2b1;
                float a = bb[j];
                #pragma unroll 8
                for (int k = 0; k < ZD; k++) a += gz[k] * w[k*C + j];
                hz[tid] = gelu_exact(a);
            }
            __syncthreads();
            {
                int j = tid & 127;
                const float* w = (tid < 128) ? z1w2 : z2w2;
                const float* bb = (tid < 128) ? z1b2 : z2b2;
                const float* h = (tid < 128) ? hz : (hz + C);
                float a = bb[j];
                #pragma unroll 8
                for (int k = 0; k < C; k++) a += h[k] * w[k*C + j];
                if (tid < 128) g_zz1[b*C + j] = a; else g_zz2[b*C + j] = a;
            }
        }
    } else {
        int i = (bid - 520) * 256 + tid;
        if (i < NCONVW) {
            int p = i & 63, rest = i >> 6;
            int cout = rest & 127, tap = rest >> 7;
            g_wct[(tap*128 + cout)*64 + p] =
                pack_h2(convw[(tap*128 + 2*p + 0)*128 + cout], convw[(tap*128 + 2*p + 1)*128 + cout]);
        } else if (i < NCONVW + NW1W) {
            int j = i - NCONVW, p = j & 63, n = j >> 6;
            g_w1t[n*64 + p] = pack_h2(w1[(2*p+0)*256 + n], w1[(2*p+1)*256 + n]);
        } else {
            int j = i - (NCONVW + NW1W), p = j & 127, n = j >> 7;
            g_w2t[n*128 + p] = pack_h2(w2[(2*p+0)*128 + n], w2[(2*p+1)*128 + n]);
        }
    }
}

// ---------------- launch 3: LN1 + modulation -> fp16 plane (plain order) ------------
__global__ void modulate1_kernel(const float* __restrict__ xf,
                                 const float* __restrict__ lnw, const float* __restrict__ lnb) {
    const int warp = threadIdx.x >> 5, lane = threadIdx.x & 31;
    const int n = blockIdx.x * 8 + warp, b = n >> 15;
    float4 v = *(const float4*)(xf + (size_t)n*C + lane*4);
    float s = v.x + v.y + v.z + v.w;
    float sq = v.x*v.x + v.y*v.y + v.z*v.z + v.w*v.w;
    #pragma unroll
    for (int o = 16; o; o >>= 1) {
        s  += __shfl_xor_sync(0xffffffffu, s,  o);
        sq += __shfl_xor_sync(0xffffffffu, sq, o);
    }
    float mu = s * (1.0f/C);
    float rs = rsqrtf(sq*(1.0f/C) - mu*mu + LN_EPS);
    float vv[4] = {v.x, v.y, v.z, v.w}, o4[4];
    #pragma unroll
    for (int u = 0; u < 4; u++) {
        int c = lane*4 + u;
        float f = (vv[u] - mu)*rs*lnw[c] + lnb[c];
        f = f*(1.0f + g_tt1[b*256 + c]) + g_tt1[b*256 + 128 + c];
        o4[u] = f*(1.0f + g_zz1[b*128 + c]);
    }
    uint2 pk = { pack_h2(o4[0], o4[1]), pack_h2(o4[2], o4[3]) };
    *(uint2*)(g_h1f + (size_t)n*64 + lane*2) = pk;
}

// ---------------- launch 4: conv — R9 pipeline + ldmatrix fragments -----------------
#define AST 36                           // row stride (words) = 144 B
#define ACHUNK (128*AST*4)               // 18432 B
#define BST 36
#define BCHUNK (128*BST*4)
#define BUFB (ACHUNK + BCHUNK)           // 36864 B
#define CONV_SMEM (2*BUFB)               // 73728 B -> 2 CTAs/SM
__device__ __forceinline__ int nbr_lookup(int myb, int myy, int myx, int tap) {
    int ny = myy + tap/7 - 3, nx = myx + tap%7 - 3;
    if ((unsigned)ny < 256u && (unsigned)nx < 256u) return g_grid[myb | (ny<<8) | nx];
    return -1;
}
__device__ __forceinline__ void stage_chunk(uint32_t Ab, uint32_t Bb, int tap, int ch,
                                            int nbr, int row, int hh) {
    const char* asrc = (const char*)g_h1f;
    uint32_t sz = 0;
    if (nbr >= 0) { asrc += (size_t)nbr*256 + ch*128 + hh*64; sz = 16; }
    uint32_t adst = Ab + row*(AST*4) + hh*64;
    #pragma unroll
    for (int j = 0; j < 4; j++) cp16(adst + j*16, asrc + j*16, sz);
    const char* bsrc = (const char*)g_wct + (size_t)(tap*128 + row)*256 + ch*128 + hh*64;
    uint32_t bdst = Bb + row*(BST*4) + hh*64;
    #pragma unroll
    for (int j = 0; j < 4; j++) cp16(bdst + j*16, bsrc + j*16, 16);
}

__global__ __launch_bounds__(256, 2) void conv_kernel(
    const float* __restrict__ xf, const float* __restrict__ nrm, const int* __restrict__ xidx) {
    extern __shared__ uint8_t smemraw[];
    const uint32_t sb32 = smem_u32(smemraw);
    const int tid = threadIdx.x, warp = tid >> 5, lane = tid & 31;
    const int wm = warp >> 1, wn = warp & 1;
    const int lq = lane >> 2, lr = lane & 3;
    const int base = blockIdx.x * 128;
    const int row = tid >> 1, hh = tid & 1;

    const int n0i = base + row;
    const int myb = xidx[3*n0i] << 16, myy = xidx[3*n0i+1], myx = xidx[3*n0i+2];

    // ldmatrix per-lane address offsets (bytes within chunk matrices)
    const uint32_t aoff = (uint32_t)(wm*32 + (lane & 15))*144 + (uint32_t)(lane >> 4)*16;
    const uint32_t boff = (uint32_t)(wn*64 + ((lane >> 4) << 3) + (lane & 7))*144
                        + (uint32_t)((lane >> 3) & 1)*16;

    float acc[2][8][4];
    #pragma unroll
    for (int mt = 0; mt < 2; mt++)
        #pragma unroll
        for (int nj = 0; nj < 8; nj++)
            #pragma unroll
            for (int q = 0; q < 4; q++) acc[mt][nj][q] = 0.0f;

    const uint32_t AbU[2] = { sb32, sb32 + BUFB };
    const uint32_t BbU[2] = { sb32 + ACHUNK, sb32 + BUFB + ACHUNK };

    int nbr_s = nbr_lookup(myb, myy, myx, 0);
    int nbr_p = -1;
    stage_chunk(AbU[0], BbU[0], 0, 0, nbr_s, row, hh);
    CP_COMMIT();

    #pragma unroll 2
    for (int c = 0; c < 98; c++) {
        const int tap = c >> 1;
        if (c < 97) {
            const int c1 = c + 1;
            int nbr_use = (c1 & 1) ? nbr_s : nbr_p;
            if ((c1 & 1) == 0) nbr_s = nbr_p;
            stage_chunk(AbU[c1 & 1], BbU[c1 & 1], c1 >> 1, c1 & 1, nbr_use, row, hh);
            CP_COMMIT();
            CP_WAIT1();
        } else {
            CP_WAIT0();
        }
        __syncthreads();
        if ((c & 1) == 0 && tap + 1 < 49)
            nbr_p = nbr_lookup(myb, myy, myx, tap + 1);

        const uint32_t Aaddr = AbU[c & 1] + aoff;
        const uint32_t Baddr = BbU[c & 1] + boff;
        #pragma unroll
        for (int ks = 0; ks < 4; ks++) {
            uint32_t a0[4], a1[4];
            LDSM4(a0, Aaddr + ks*32);
            LDSM4(a1, Aaddr + 2304 + ks*32);        // +16 rows * 144B
            uint32_t bq[4][4];
            #pragma unroll
            for (int njp = 0; njp < 4; njp++)
                LDSM4(bq[njp], Baddr + (uint32_t)njp*2304 + ks*32);  // +16 n-rows per x4 load
            #pragma unroll
            for (int njp = 0; njp < 4; njp++)
                #pragma unroll
                for (int h = 0; h < 2; h++) {
                    mma_f16(acc[0][njp*2 + h], a0, &bq[njp][2*h]);
                    mma_f16(acc[1][njp*2 + h], a1, &bq[njp][2*h]);
                }
        }
        __syncthreads();
    }

    #pragma unroll
    for (int mt = 0; mt < 2; mt++) {
        int m = wm*32 + mt*16 + lq;
        float inv0 = 1.0f / nrm[base + m];
        float inv8 = 1.0f / nrm[base + m + 8];
        #pragma unroll
        for (int nj = 0; nj < 8; nj++) {
            int nn = wn*64 + nj*8 + lr*2;
            int gm = base + m;
            float2 x0 = *(const float2*)(xf + (size_t)gm*C + nn);
            float2 o0 = { x0.x + acc[mt][nj][0]*inv0, x0.y + acc[mt][nj][1]*inv0 };
            *(float2*)(g_x + (size_t)gm*C + nn) = o0;
            gm += 8;
            float2 x1 = *(const float2*)(xf + (size_t)gm*C + nn);
            float2 o1 = { x1.x + acc[mt][nj][2]*inv8, x1.y + acc[mt][nj][3]*inv8 };
            *(float2*)(g_x + (size_t)gm*C + nn) = o1;
        }
    }
}

// ---------------- launch 5: LN2 + modulation + MLP (pure fp16) + residual -----------
#define AST2 68
#define HST  132
#define MLP_SMEM ((64*AST2 + 64*HST) * 4)    // 51200 B
__global__ __launch_bounds__(256) void mlp_kernel(
    const float* __restrict__ lnw, const float* __restrict__ lnb,
    const float* __restrict__ b1,  const float* __restrict__ b2, float* __restrict__ out) {
    extern __shared__ uint32_t smem[];
    uint32_t* As = smem;
    uint32_t* Hs = smem + 64 * AST2;
    const int tid = threadIdx.x, warp = tid >> 5, lane = tid & 31;
    const int lq = lane >> 2, lr = lane & 3;
    const int base = blockIdx.x * 64;

    #pragma unroll
    for (int rr = 0; rr < 8; rr++) {
        int rl = warp*8 + rr, n = base + rl, b = n >> 15;
        float4 v = *(const float4*)(g_x + (size_t)n*C + lane*4);
        float s = v.x+v.y+v.z+v.w, sq = v.x*v.x+v.y*v.y+v.z*v.z+v.w*v.w;
        #pragma unroll
        for (int o = 16; o; o >>= 1) {
            s  += __shfl_xor_sync(0xffffffffu, s,  o);
            sq += __shfl_xor_sync(0xffffffffu, sq, o);
        }
        float mu = s*(1.0f/C), rs = rsqrtf(sq*(1.0f/C) - mu*mu + LN_EPS);
        float vv[4] = {v.x,v.y,v.z,v.w}, o4[4];
        #pragma unroll
        for (int u = 0; u < 4; u++) {
            int c = lane*4 + u;
            float f = (vv[u]-mu)*rs*lnw[c] + lnb[c];
            f = f*(1.0f + g_tt2[b*256+c]) + g_tt2[b*256+128+c];
            o4[u] = f*(1.0f + g_zz2[b*128+c]);
        }
        uint2 pk = { pack_h2(o4[0], o4[1]), pack_h2(o4[2], o4[3]) };
        *(uint2*)(As + rl*AST2 + lane*2) = pk;
    }
    __syncthreads();

    float acc1[4][4][4];
    #pragma unroll
    for (int mt = 0; mt < 4; mt++)
        #pragma unroll
        for (int nj = 0; nj < 4; nj++)
            #pragma unroll
            for (int q = 0; q < 4; q++) acc1[mt][nj][q] = 0.0f;
    #pragma unroll
    for (int ks = 0; ks < 8; ks++) {
        uint32_t a[4][4];
        #pragma unroll
        for (int mt = 0; mt < 4; mt++) {
            const uint32_t* ap = As + (mt*16 + lq)*AST2 + ks*8 + lr;
            a[mt][0] = ap[0]; a[mt][1] = ap[8*AST2]; a[mt][2] = ap[4]; a[mt][3] = ap[8*AST2 + 4];
        }
        #pragma unroll
        for (int nj = 0; nj < 4; nj++) {
            const uint32_t* bp = g_w1t + (warp*32 + nj*8 + lq)*64 + ks*8 + lr;
            uint32_t b[2] = { bp[0], bp[4] };
            #pragma unroll
            for (int mt = 0; mt < 4; mt++)
                mma_f16(acc1[mt][nj], a[mt], b);
        }
    }
    #pragma unroll
    for (int nj = 0; nj < 4; nj++) {
        int nn = warp*32 + nj*8 + lr*2;
        float2 bb = *(const float2*)(b1 + nn);
        int wrd = warp*16 + nj*4 + lr;
        #pragma unroll
        for (int mt = 0; mt < 4; mt++) {
            int m0 = mt*16 + lq;
            Hs[m0*HST + wrd]     = pack_h2(gelu_exact(acc1[mt][nj][0]+bb.x), gelu_exact(acc1[mt][nj][1]+bb.y));
            Hs[(m0+8)*HST + wrd] = pack_h2(gelu_exact(acc1[mt][nj][2]+bb.x), gelu_exact(acc1[mt][nj][3]+bb.y));
        }
    }
    __syncthreads();

    float acc2[4][2][4];
    #pragma unroll
    for (int mt = 0; mt < 4; mt++)
        #pragma unroll
        for (int nj = 0; nj < 2; nj++)
            #pragma unroll
            for (int q = 0; q < 4; q++) acc2[mt][nj][q] = 0.0f;
    #pragma unroll
    for (int ks = 0; ks < 16; ks++) {
        uint32_t a[4][4];
        #pragma unroll
        for (int mt = 0; mt < 4; mt++) {
            const uint32_t* ap = Hs + (mt*16 + lq)*HST + ks*8 + lr;
            a[mt][0] = ap[0]; a[mt][1] = ap[8*HST]; a[mt][2] = ap[4]; a[mt][3] = ap[8*HST + 4];
        }
        #pragma unroll
        for (int nj = 0; nj < 2; nj++) {
            const uint32_t* bp = g_w2t + (warp*16 + nj*8 + lq)*128 + ks*8 + lr;
            uint32_t b[2] = { bp[0], bp[4] };
            #pragma unroll
            for (int mt = 0; mt < 4; mt++)
                mma_f16(acc2[mt][nj], a[mt], b);
        }
    }
    #pragma unroll
    for (int nj = 0; nj < 2; nj++) {
        int nn = warp*16 + nj*8 + lr*2;
        float2 bb = *(const float2*)(b2 + nn);
        #pragma unroll
        for (int mt = 0; mt < 4; mt++) {
            int m0 = mt*16 + lq;
            int gm = base + m0;
            float2 x = *(const float2*)(g_x + (size_t)gm*C + nn);
            float2 o = { x.x + acc2[mt][nj][0] + bb.x, x.y + acc2[mt][nj][1] + bb.y };
            *(float2*)(out + (size_t)gm*C + nn) = o;
            gm += 8;
            x = *(const float2*)(g_x + (size_t)gm*C + nn);
            o.x = x.x + acc2[mt][nj][2] + bb.x;
            o.y = x.y + acc2[mt][nj][3] + bb.y;
            *(float2*)(out + (size_t)gm*C + nn) = o;
        }
    }
}

extern "C" void kernel_launch(void* const* d_in, const int* in_sizes, int n_in,
                              void* d_out, int out_size) {
    const float* xf    = (const float*)d_in[0];
    const int*   xi    = (const int*)  d_in[1];
    const float* t     = (const float*)d_in[2];
    const float* z     = (const float*)d_in[3];
    const float* nrm   = (const float*)d_in[4];
    const float* ln1w  = (const float*)d_in[5];
    const float* ln1b  = (const float*)d_in[6];
    const float* ln2w  = (const float*)d_in[7];
    const float* ln2b  = (const float*)d_in[8];
    const float* convw = (const float*)d_in[9];
    const float* t1w   = (const float*)d_in[10];
    const float* t1b   = (const float*)d_in[11];
    const float* t2w   = (const float*)d_in[12];
    const float* t2b   = (const float*)d_in[13];
    const float* z1w1  = (const float*)d_in[14];
    const float* z1b1  = (const float*)d_in[15];
    const float* z1w2  = (const float*)d_in[16];
    const float* z1b2  = (const float*)d_in[17];
    const float* z2w1  = (const float*)d_in[18];
    const float* z2b1  = (const float*)d_in[19];
    const float* z2w2  = (const float*)d_in[20];
    const float* z2b2  = (const float*)d_in[21];
    const float* w1    = (const float*)d_in[22];
    const float* b1    = (const float*)d_in[23];
    const float* w2    = (const float*)d_in[24];
    const float* b2    = (const float*)d_in[25];
    float* out = (float*)d_out;

    cudaFuncSetAttribute(conv_kernel, cudaFuncAttributeMaxDynamicSharedMemorySize, CONV_SMEM);
    cudaFuncSetAttribute(mlp_kernel,  cudaFuncAttributeMaxDynamicSharedMemorySize, MLP_SMEM);

    fill_grid_kernel<<<(NBATCH*IMG*IMG)/256, 256>>>();
    fused_init_kernel<<<512 + 8 + SPLIT_BLKS, 256>>>(xi, t, z, t1w, t1b, t2w, t2b,
        z1w1, z1b1, z1w2, z1b2, z2w1, z2b1, z2w2, z2b2, convw, w1, w2);
    modulate1_kernel<<<NPTS/8, 256>>>(xf, ln1w, ln1b);
    conv_kernel<<<NPTS/128, 256, CONV_SMEM>>>(xf, nrm, xi);
    mlp_kernel<<<NPTS/64, 256, MLP_SMEM>>>(ln2w, ln2b, b1, b2, out);
    (void)in_sizes; (void)n_in; (void)out_size;
}